// round 1
// baseline (speedup 1.0000x reference)
#include <cuda_runtime.h>
#include <cstdint>

// Problem shape (fixed for this instance)
#define NUM_SP 2048
#define CCH    64
#define NPIX   (1024 * 1024)

// Scratch (allocation-free rule: __device__ globals)
__device__ float g_sums[NUM_SP * CCH];   // [S, C] row-major, 512 KB (L2-resident)
__device__ float g_cnt[NUM_SP];          // pixel counts per segment
__device__ float g_means[NUM_SP * CCH];  // [S, C]

// -------------------------------------------------------------------------
// Kernel 1: zero scratch
// -------------------------------------------------------------------------
__global__ void zero_kernel() {
    int i = blockIdx.x * blockDim.x + threadIdx.x;
    if (i < NUM_SP * CCH) g_sums[i] = 0.0f;
    if (i < NUM_SP)       g_cnt[i]  = 0.0f;
}

// -------------------------------------------------------------------------
// Vectorized global reduction: one RED instruction for 4 consecutive floats.
// sm_90+ PTX: red.global.add.v4.f32
// -------------------------------------------------------------------------
__device__ __forceinline__ void red_add_v4(float* addr, float a, float b,
                                           float c, float d) {
    asm volatile("red.global.add.v4.f32 [%0], {%1, %2, %3, %4};"
                 :: "l"(addr), "f"(a), "f"(b), "f"(c), "f"(d)
                 : "memory");
}

// -------------------------------------------------------------------------
// Kernel 2: accumulate sums + counts.
// Each thread: 4 consecutive pixels x all 64 channels.
//   - x loads are float4 along pixel dim (coalesced LDG.128)
//   - 4x4 in-register transpose -> red.v4 along channel dim into sums rows
// -------------------------------------------------------------------------
__global__ void __launch_bounds__(256) accum_kernel(
    const float* __restrict__ x, const int* __restrict__ sp) {
    int t = blockIdx.x * blockDim.x + threadIdx.x;  // 0 .. NPIX/4 - 1
    int p = t * 4;
    if (p >= NPIX) return;

    int4 s4 = *reinterpret_cast<const int4*>(sp + p);

    // Counts: one scalar RED per pixel (1M total, cheap)
    atomicAdd(&g_cnt[s4.x], 1.0f);
    atomicAdd(&g_cnt[s4.y], 1.0f);
    atomicAdd(&g_cnt[s4.z], 1.0f);
    atomicAdd(&g_cnt[s4.w], 1.0f);

    float* r0 = &g_sums[(size_t)s4.x * CCH];
    float* r1 = &g_sums[(size_t)s4.y * CCH];
    float* r2 = &g_sums[(size_t)s4.z * CCH];
    float* r3 = &g_sums[(size_t)s4.w * CCH];

#pragma unroll
    for (int cg = 0; cg < CCH; cg += 4) {
        // v{j} = x[channel cg+j][pixels p..p+3]
        float4 v0 = *reinterpret_cast<const float4*>(x + (size_t)(cg + 0) * NPIX + p);
        float4 v1 = *reinterpret_cast<const float4*>(x + (size_t)(cg + 1) * NPIX + p);
        float4 v2 = *reinterpret_cast<const float4*>(x + (size_t)(cg + 2) * NPIX + p);
        float4 v3 = *reinterpret_cast<const float4*>(x + (size_t)(cg + 3) * NPIX + p);

        // Transpose: pixel k accumulates channels (cg..cg+3)
        red_add_v4(r0 + cg, v0.x, v1.x, v2.x, v3.x);
        red_add_v4(r1 + cg, v0.y, v1.y, v2.y, v3.y);
        red_add_v4(r2 + cg, v0.z, v1.z, v2.z, v3.z);
        red_add_v4(r3 + cg, v0.w, v1.w, v2.w, v3.w);
    }
}

// -------------------------------------------------------------------------
// Kernel 3: means = sums / max(count, 1)
// -------------------------------------------------------------------------
__global__ void means_kernel() {
    int i = blockIdx.x * blockDim.x + threadIdx.x;
    if (i >= NUM_SP * CCH) return;
    int s = i / CCH;
    g_means[i] = g_sums[i] / fmaxf(g_cnt[s], 1.0f);
}

// -------------------------------------------------------------------------
// Kernel 4: gather/broadcast means back to pixels.
// Each thread: 4 consecutive pixels x all 64 channels.
//   - means rows read as float4 (L2-resident, 512 KB)
//   - 4x4 transpose -> STG.128 per channel (coalesced along pixel dim)
// -------------------------------------------------------------------------
__global__ void __launch_bounds__(256) gather_kernel(
    const int* __restrict__ sp, float* __restrict__ out) {
    int t = blockIdx.x * blockDim.x + threadIdx.x;
    int p = t * 4;
    if (p >= NPIX) return;

    int4 s4 = *reinterpret_cast<const int4*>(sp + p);
    const float4* m0 = reinterpret_cast<const float4*>(&g_means[(size_t)s4.x * CCH]);
    const float4* m1 = reinterpret_cast<const float4*>(&g_means[(size_t)s4.y * CCH]);
    const float4* m2 = reinterpret_cast<const float4*>(&g_means[(size_t)s4.z * CCH]);
    const float4* m3 = reinterpret_cast<const float4*>(&g_means[(size_t)s4.w * CCH]);

#pragma unroll
    for (int cg = 0; cg < CCH / 4; cg++) {
        float4 a = m0[cg];  // channels 4cg..4cg+3 of pixel p+0's segment
        float4 b = m1[cg];
        float4 c = m2[cg];
        float4 d = m3[cg];

        *reinterpret_cast<float4*>(out + (size_t)(cg * 4 + 0) * NPIX + p) =
            make_float4(a.x, b.x, c.x, d.x);
        *reinterpret_cast<float4*>(out + (size_t)(cg * 4 + 1) * NPIX + p) =
            make_float4(a.y, b.y, c.y, d.y);
        *reinterpret_cast<float4*>(out + (size_t)(cg * 4 + 2) * NPIX + p) =
            make_float4(a.z, b.z, c.z, d.z);
        *reinterpret_cast<float4*>(out + (size_t)(cg * 4 + 3) * NPIX + p) =
            make_float4(a.w, b.w, c.w, d.w);
    }
}

// -------------------------------------------------------------------------
// kernel_launch: graph-capturable (kernel launches only)
// Inputs (metadata order): x fp32 [C,H,W], sp int32 [H,W], num_segments int
// -------------------------------------------------------------------------
extern "C" void kernel_launch(void* const* d_in, const int* in_sizes, int n_in,
                              void* d_out, int out_size) {
    const float* x  = (const float*)d_in[0];
    const int*   sp = (const int*)d_in[1];
    float*       out = (float*)d_out;

    const int threads = 256;
    const int zero_blocks   = (NUM_SP * CCH + threads - 1) / threads;
    const int pix_blocks    = (NPIX / 4 + threads - 1) / threads;
    const int means_blocks  = (NUM_SP * CCH + threads - 1) / threads;

    zero_kernel<<<zero_blocks, threads>>>();
    accum_kernel<<<pix_blocks, threads>>>(x, sp);
    means_kernel<<<means_blocks, threads>>>();
    gather_kernel<<<pix_blocks, threads>>>(sp, out);
}

// round 2
// speedup vs baseline: 1.0072x; 1.0072x over previous
#include <cuda_runtime.h>
#include <cstdint>

// Problem shape (fixed for this instance)
#define NUM_SP 2048
#define CCH    64
#define NPIX   (1024 * 1024)

// Scratch (allocation-free rule: __device__ globals)
__device__ float g_sums[NUM_SP * CCH];   // [S, C] row-major, 512 KB (L2-resident)
__device__ float g_cnt[NUM_SP];          // pixel counts per segment
__device__ float g_means[NUM_SP * CCH];  // [S, C]

// -------------------------------------------------------------------------
// Kernel 1: zero scratch
// -------------------------------------------------------------------------
__global__ void zero_kernel() {
    int i = blockIdx.x * blockDim.x + threadIdx.x;
    if (i < NUM_SP * CCH) g_sums[i] = 0.0f;
    if (i < NUM_SP)       g_cnt[i]  = 0.0f;
}

// -------------------------------------------------------------------------
// Vectorized global reduction: one RED for 4 consecutive floats (sm_90+).
// Fire-and-forget: no scoreboard wait on the consumer side.
// -------------------------------------------------------------------------
__device__ __forceinline__ void red_add_v4(float* addr, float a, float b,
                                           float c, float d) {
    asm volatile("red.global.add.v4.f32 [%0], {%1, %2, %3, %4};"
                 :: "l"(addr), "f"(a), "f"(b), "f"(c), "f"(d)
                 : "memory");
}

// -------------------------------------------------------------------------
// Kernel 2: accumulate sums (+counts from the y==0 slice).
// 2D grid: blockIdx.x covers pixel quads, blockIdx.y covers channel groups
// of 4. Each thread: 4 consecutive pixels x 4 channels.
//   - 1x int4 sp load (L2-resident, shared across all y-slices)
//   - 4x LDG.128 on x (coalesced along pixels)
//   - 4x4 register transpose -> 4x RED.v4 into sums rows
// Small per-thread footprint -> high occupancy -> deep MLP to cover the
// scattered-L2/atomic latency that bound R1.
// -------------------------------------------------------------------------
__global__ void __launch_bounds__(256) accum_kernel(
    const float* __restrict__ x, const int* __restrict__ sp) {
    int t = blockIdx.x * blockDim.x + threadIdx.x;  // pixel-quad index
    int p = t * 4;
    int cg = blockIdx.y * 4;                        // first channel of group

    int4 s4 = *reinterpret_cast<const int4*>(sp + p);

    if (blockIdx.y == 0) {
        atomicAdd(&g_cnt[s4.x], 1.0f);
        atomicAdd(&g_cnt[s4.y], 1.0f);
        atomicAdd(&g_cnt[s4.z], 1.0f);
        atomicAdd(&g_cnt[s4.w], 1.0f);
    }

    // v{j} = x[channel cg+j][pixels p..p+3]
    float4 v0 = *reinterpret_cast<const float4*>(x + (size_t)(cg + 0) * NPIX + p);
    float4 v1 = *reinterpret_cast<const float4*>(x + (size_t)(cg + 1) * NPIX + p);
    float4 v2 = *reinterpret_cast<const float4*>(x + (size_t)(cg + 2) * NPIX + p);
    float4 v3 = *reinterpret_cast<const float4*>(x + (size_t)(cg + 3) * NPIX + p);

    red_add_v4(&g_sums[(size_t)s4.x * CCH + cg], v0.x, v1.x, v2.x, v3.x);
    red_add_v4(&g_sums[(size_t)s4.y * CCH + cg], v0.y, v1.y, v2.y, v3.y);
    red_add_v4(&g_sums[(size_t)s4.z * CCH + cg], v0.z, v1.z, v2.z, v3.z);
    red_add_v4(&g_sums[(size_t)s4.w * CCH + cg], v0.w, v1.w, v2.w, v3.w);
}

// -------------------------------------------------------------------------
// Kernel 3: means = sums / max(count, 1)
// -------------------------------------------------------------------------
__global__ void means_kernel() {
    int i = blockIdx.x * blockDim.x + threadIdx.x;
    if (i >= NUM_SP * CCH) return;
    int s = i / CCH;
    g_means[i] = g_sums[i] / fmaxf(g_cnt[s], 1.0f);
}

// -------------------------------------------------------------------------
// Kernel 4: gather/broadcast means back to pixels.
// Same 2D decomposition: 4 pixels x 4 channels per thread.
//   - 4 scattered float4 loads from means (L2-resident, 512 KB)
//   - 4x4 transpose -> 4 coalesced STG.128
// -------------------------------------------------------------------------
__global__ void __launch_bounds__(256) gather_kernel(
    const int* __restrict__ sp, float* __restrict__ out) {
    int t = blockIdx.x * blockDim.x + threadIdx.x;
    int p = t * 4;
    int cg = blockIdx.y;  // channel group index (float4 granularity)

    int4 s4 = *reinterpret_cast<const int4*>(sp + p);

    float4 a = __ldg(reinterpret_cast<const float4*>(&g_means[(size_t)s4.x * CCH]) + cg);
    float4 b = __ldg(reinterpret_cast<const float4*>(&g_means[(size_t)s4.y * CCH]) + cg);
    float4 c = __ldg(reinterpret_cast<const float4*>(&g_means[(size_t)s4.z * CCH]) + cg);
    float4 d = __ldg(reinterpret_cast<const float4*>(&g_means[(size_t)s4.w * CCH]) + cg);

    *reinterpret_cast<float4*>(out + (size_t)(cg * 4 + 0) * NPIX + p) =
        make_float4(a.x, b.x, c.x, d.x);
    *reinterpret_cast<float4*>(out + (size_t)(cg * 4 + 1) * NPIX + p) =
        make_float4(a.y, b.y, c.y, d.y);
    *reinterpret_cast<float4*>(out + (size_t)(cg * 4 + 2) * NPIX + p) =
        make_float4(a.z, b.z, c.z, d.z);
    *reinterpret_cast<float4*>(out + (size_t)(cg * 4 + 3) * NPIX + p) =
        make_float4(a.w, b.w, c.w, d.w);
}

// -------------------------------------------------------------------------
// kernel_launch: graph-capturable (kernel launches only)
// Inputs (metadata order): x fp32 [C,H,W], sp int32 [H,W], num_segments int
// -------------------------------------------------------------------------
extern "C" void kernel_launch(void* const* d_in, const int* in_sizes, int n_in,
                              void* d_out, int out_size) {
    const float* x  = (const float*)d_in[0];
    const int*   sp = (const int*)d_in[1];
    float*       out = (float*)d_out;

    const int threads = 256;
    const int zero_blocks  = (NUM_SP * CCH + threads - 1) / threads;
    const int quad_blocks  = (NPIX / 4) / threads;        // 1024
    const int means_blocks = (NUM_SP * CCH + threads - 1) / threads;

    zero_kernel<<<zero_blocks, threads>>>();
    accum_kernel<<<dim3(quad_blocks, CCH / 4), threads>>>(x, sp);
    means_kernel<<<means_blocks, threads>>>();
    gather_kernel<<<dim3(quad_blocks, CCH / 4), threads>>>(sp, out);
}

// round 3
// speedup vs baseline: 1.1450x; 1.1369x over previous
#include <cuda_runtime.h>
#include <cstdint>

// Problem shape (fixed for this instance)
#define NUM_SP 2048
#define CCH    64
#define NPIX   (1024 * 1024)

// Gather tiling: each block handles QITER*256 pixel-quads for one 4-channel group
#define QITER  16                          // quads per thread
#define PIX_PER_BLOCK (QITER * 256 * 4)    // 16384 pixels

// Scratch (allocation-free rule: __device__ globals)
__device__ float g_sums[NUM_SP * CCH];   // [S, C] row-major, 512 KB (L2-resident)
__device__ float g_cnt[NUM_SP];          // pixel counts per segment

// -------------------------------------------------------------------------
// Kernel 1: zero scratch
// -------------------------------------------------------------------------
__global__ void zero_kernel() {
    int i = blockIdx.x * blockDim.x + threadIdx.x;
    if (i < NUM_SP * CCH) g_sums[i] = 0.0f;
    if (i < NUM_SP)       g_cnt[i]  = 0.0f;
}

// -------------------------------------------------------------------------
// Vectorized fire-and-forget global reduction (sm_90+).
// -------------------------------------------------------------------------
__device__ __forceinline__ void red_add_v4(float* addr, float a, float b,
                                           float c, float d) {
    asm volatile("red.global.add.v4.f32 [%0], {%1, %2, %3, %4};"
                 :: "l"(addr), "f"(a), "f"(b), "f"(c), "f"(d)
                 : "memory");
}

// -------------------------------------------------------------------------
// Kernel 2: accumulate sums (+counts from the y==0 slice).
// 2D grid: blockIdx.x covers pixel quads, blockIdx.y covers channel groups.
// Each thread: 4 consecutive pixels x 4 channels.
// -------------------------------------------------------------------------
__global__ void __launch_bounds__(256) accum_kernel(
    const float* __restrict__ x, const int* __restrict__ sp) {
    int t = blockIdx.x * blockDim.x + threadIdx.x;  // pixel-quad index
    int p = t * 4;
    int cg = blockIdx.y * 4;                        // first channel of group

    int4 s4 = *reinterpret_cast<const int4*>(sp + p);

    if (blockIdx.y == 0) {
        atomicAdd(&g_cnt[s4.x], 1.0f);
        atomicAdd(&g_cnt[s4.y], 1.0f);
        atomicAdd(&g_cnt[s4.z], 1.0f);
        atomicAdd(&g_cnt[s4.w], 1.0f);
    }

    float4 v0 = *reinterpret_cast<const float4*>(x + (size_t)(cg + 0) * NPIX + p);
    float4 v1 = *reinterpret_cast<const float4*>(x + (size_t)(cg + 1) * NPIX + p);
    float4 v2 = *reinterpret_cast<const float4*>(x + (size_t)(cg + 2) * NPIX + p);
    float4 v3 = *reinterpret_cast<const float4*>(x + (size_t)(cg + 3) * NPIX + p);

    red_add_v4(&g_sums[(size_t)s4.x * CCH + cg], v0.x, v1.x, v2.x, v3.x);
    red_add_v4(&g_sums[(size_t)s4.y * CCH + cg], v0.y, v1.y, v2.y, v3.y);
    red_add_v4(&g_sums[(size_t)s4.z * CCH + cg], v0.z, v1.z, v2.z, v3.z);
    red_add_v4(&g_sums[(size_t)s4.w * CCH + cg], v0.w, v1.w, v2.w, v3.w);
}

// -------------------------------------------------------------------------
// Kernel 3: gather/broadcast, smem-staged means.
// grid = (NPIX / PIX_PER_BLOCK, CCH/4). Each block:
//   1. stages means[s][cg..cg+3] for ALL 2048 segments into 32 KB smem
//      (computed from g_sums / max(g_cnt,1) — means kernel fused away)
//   2. loops QITER quads: random-address LDS.128 (smem crossbar, no L1 tag
//      storm), 4x4 transpose, 4 coalesced STG.128 to out.
// -------------------------------------------------------------------------
__global__ void __launch_bounds__(256) gather_kernel(
    const int* __restrict__ sp, float* __restrict__ out) {
    __shared__ float4 s_means[NUM_SP];   // 32 KB: segment -> 4-channel mean

    int tid = threadIdx.x;
    int cg  = blockIdx.y;                // channel group (float4 granularity)
    int blockPixBase = blockIdx.x * PIX_PER_BLOCK;

    // Stage: each thread computes means for 8 segments
#pragma unroll
    for (int i = 0; i < NUM_SP / 256; i++) {
        int s = i * 256 + tid;
        float4 sum = *reinterpret_cast<const float4*>(
            &g_sums[(size_t)s * CCH + cg * 4]);
        float inv = __frcp_rn(fmaxf(g_cnt[s], 1.0f));
        s_means[s] = make_float4(sum.x * inv, sum.y * inv, sum.z * inv, sum.w * inv);
    }
    __syncthreads();

#pragma unroll
    for (int q = 0; q < QITER; q++) {
        int p = blockPixBase + (q * 256 + tid) * 4;
        int4 s4 = *reinterpret_cast<const int4*>(sp + p);

        float4 a = s_means[s4.x];
        float4 b = s_means[s4.y];
        float4 c = s_means[s4.z];
        float4 d = s_means[s4.w];

        *reinterpret_cast<float4*>(out + (size_t)(cg * 4 + 0) * NPIX + p) =
            make_float4(a.x, b.x, c.x, d.x);
        *reinterpret_cast<float4*>(out + (size_t)(cg * 4 + 1) * NPIX + p) =
            make_float4(a.y, b.y, c.y, d.y);
        *reinterpret_cast<float4*>(out + (size_t)(cg * 4 + 2) * NPIX + p) =
            make_float4(a.z, b.z, c.z, d.z);
        *reinterpret_cast<float4*>(out + (size_t)(cg * 4 + 3) * NPIX + p) =
            make_float4(a.w, b.w, c.w, d.w);
    }
}

// -------------------------------------------------------------------------
// kernel_launch: graph-capturable (kernel launches only)
// Inputs (metadata order): x fp32 [C,H,W], sp int32 [H,W], num_segments int
// -------------------------------------------------------------------------
extern "C" void kernel_launch(void* const* d_in, const int* in_sizes, int n_in,
                              void* d_out, int out_size) {
    const float* x  = (const float*)d_in[0];
    const int*   sp = (const int*)d_in[1];
    float*       out = (float*)d_out;

    const int threads = 256;
    const int zero_blocks = (NUM_SP * CCH + threads - 1) / threads;
    const int quad_blocks = (NPIX / 4) / threads;          // 1024

    zero_kernel<<<zero_blocks, threads>>>();
    accum_kernel<<<dim3(quad_blocks, CCH / 4), threads>>>(x, sp);
    gather_kernel<<<dim3(NPIX / PIX_PER_BLOCK, CCH / 4), threads>>>(sp, out);
}

// round 4
// speedup vs baseline: 1.6026x; 1.3996x over previous
#include <cuda_runtime.h>
#include <cstdint>

// Problem shape (fixed for this instance)
#define NUM_SP 2048
#define CCH    64
#define NPIX   (1024 * 1024)

// Accum tiling: 64 pixels x 64 channels per block, staged through smem
#define TILE_PX 64

// Gather tiling: each block handles QITER*256 pixel-quads for one 4-channel group
#define QITER  16
#define PIX_PER_BLOCK (QITER * 256 * 4)    // 16384 pixels

// Scratch (allocation-free rule: __device__ globals)
__device__ float g_sums[NUM_SP * CCH];   // [S, C] row-major, 512 KB (L2-resident)
__device__ float g_cnt[NUM_SP];          // pixel counts per segment

// -------------------------------------------------------------------------
// Kernel 1: zero scratch
// -------------------------------------------------------------------------
__global__ void zero_kernel() {
    int i = blockIdx.x * blockDim.x + threadIdx.x;
    if (i < NUM_SP * CCH) g_sums[i] = 0.0f;
    if (i < NUM_SP)       g_cnt[i]  = 0.0f;
}

// -------------------------------------------------------------------------
// Vectorized fire-and-forget global reduction (sm_90+).
// -------------------------------------------------------------------------
__device__ __forceinline__ void red_add_v4(float* addr, float a, float b,
                                           float c, float d) {
    asm volatile("red.global.add.v4.f32 [%0], {%1, %2, %3, %4};"
                 :: "l"(addr), "f"(a), "f"(b), "f"(c), "f"(d)
                 : "memory");
}

// -------------------------------------------------------------------------
// Kernel 2: accumulate sums + counts, line-coalesced REDs.
// Block = 256 threads, tile = 64 pixels x 64 channels.
//
// Phase 1: coalesced LDG.128 on x (float4 along pixels), scatter-store into
//   an XOR-swizzled smem transpose buffer s_t[px][c4] (c4 = channel group
//   of 4). Swizzle c4 ^ ((px>>2)&15) makes the scalar STS pattern
//   conflict-free (16 half-warp lanes -> 16 distinct banks).
//
// Phase 2: (px, cg) pairs mapped so lanes 0-15 of a warp cover all 16
//   channel groups of ONE pixel (lanes 16-31: the next pixel). Each warp's
//   RED.v4 then targets 2 segment rows x 256 B = 4 cache lines instead of
//   32 -> 8x fewer L1tex wavefronts than the R3 scheme.
// -------------------------------------------------------------------------
__global__ void __launch_bounds__(256) accum_kernel(
    const float* __restrict__ x, const int* __restrict__ sp) {
    __shared__ float4 s_t[TILE_PX * 16];   // 16 KB, swizzled [px][c4]
    __shared__ int    s_seg[TILE_PX];

    int t  = threadIdx.x;
    int p0 = blockIdx.x * TILE_PX;

    // Stage segment labels (64 ints via 16 int4 loads)
    if (t < TILE_PX / 4) {
        int4 v = reinterpret_cast<const int4*>(sp + p0)[t];
        s_seg[t * 4 + 0] = v.x;
        s_seg[t * 4 + 1] = v.y;
        s_seg[t * 4 + 2] = v.z;
        s_seg[t * 4 + 3] = v.w;
    }

    // Phase 1: load x tile coalesced, transpose into smem
    float* s_f = reinterpret_cast<float*>(s_t);
#pragma unroll
    for (int i = 0; i < 4; i++) {
        int idx = i * 256 + t;          // 0..1023
        int c   = idx >> 4;             // channel 0..63
        int f   = idx & 15;             // float4 column (4 pixels each)
        float4 v = *reinterpret_cast<const float4*>(
            x + (size_t)c * NPIX + p0 + f * 4);
        int c4   = c >> 2;
        int comp = c & 3;
#pragma unroll
        for (int k = 0; k < 4; k++) {
            int px   = f * 4 + k;
            int slot = px * 16 + (c4 ^ ((px >> 2) & 15));
            s_f[slot * 4 + comp] = (&v.x)[k];
        }
    }
    __syncthreads();

    // Phase 2: line-coalesced REDs
#pragma unroll
    for (int r = 0; r < 4; r++) {
        int pair = r * 256 + t;         // 0..1023
        int px   = pair >> 4;           // lanes 0-15 same px, 16-31 next px
        int cg   = pair & 15;           // channel group
        int seg  = s_seg[px];
        float4 v = s_t[px * 16 + (cg ^ ((px >> 2) & 15))];
        if (cg == 0) atomicAdd(&g_cnt[seg], 1.0f);
        red_add_v4(&g_sums[(size_t)seg * CCH + cg * 4], v.x, v.y, v.z, v.w);
    }
}

// -------------------------------------------------------------------------
// Kernel 3: gather/broadcast, smem-staged means (R3 version, protected win).
// -------------------------------------------------------------------------
__global__ void __launch_bounds__(256) gather_kernel(
    const int* __restrict__ sp, float* __restrict__ out) {
    __shared__ float4 s_means[NUM_SP];   // 32 KB: segment -> 4-channel mean

    int tid = threadIdx.x;
    int cg  = blockIdx.y;                // channel group (float4 granularity)
    int blockPixBase = blockIdx.x * PIX_PER_BLOCK;

    // Stage: each thread computes means for 8 segments (division fused here)
#pragma unroll
    for (int i = 0; i < NUM_SP / 256; i++) {
        int s = i * 256 + tid;
        float4 sum = *reinterpret_cast<const float4*>(
            &g_sums[(size_t)s * CCH + cg * 4]);
        float inv = __frcp_rn(fmaxf(g_cnt[s], 1.0f));
        s_means[s] = make_float4(sum.x * inv, sum.y * inv, sum.z * inv, sum.w * inv);
    }
    __syncthreads();

#pragma unroll
    for (int q = 0; q < QITER; q++) {
        int p = blockPixBase + (q * 256 + tid) * 4;
        int4 s4 = *reinterpret_cast<const int4*>(sp + p);

        float4 a = s_means[s4.x];
        float4 b = s_means[s4.y];
        float4 c = s_means[s4.z];
        float4 d = s_means[s4.w];

        *reinterpret_cast<float4*>(out + (size_t)(cg * 4 + 0) * NPIX + p) =
            make_float4(a.x, b.x, c.x, d.x);
        *reinterpret_cast<float4*>(out + (size_t)(cg * 4 + 1) * NPIX + p) =
            make_float4(a.y, b.y, c.y, d.y);
        *reinterpret_cast<float4*>(out + (size_t)(cg * 4 + 2) * NPIX + p) =
            make_float4(a.z, b.z, c.z, d.z);
        *reinterpret_cast<float4*>(out + (size_t)(cg * 4 + 3) * NPIX + p) =
            make_float4(a.w, b.w, c.w, d.w);
    }
}

// -------------------------------------------------------------------------
// kernel_launch: graph-capturable (kernel launches only)
// Inputs (metadata order): x fp32 [C,H,W], sp int32 [H,W], num_segments int
// -------------------------------------------------------------------------
extern "C" void kernel_launch(void* const* d_in, const int* in_sizes, int n_in,
                              void* d_out, int out_size) {
    const float* x  = (const float*)d_in[0];
    const int*   sp = (const int*)d_in[1];
    float*       out = (float*)d_out;

    const int threads = 256;
    const int zero_blocks  = (NUM_SP * CCH + threads - 1) / threads;
    const int accum_blocks = NPIX / TILE_PX;               // 16384

    zero_kernel<<<zero_blocks, threads>>>();
    accum_kernel<<<accum_blocks, threads>>>(x, sp);
    gather_kernel<<<dim3(NPIX / PIX_PER_BLOCK, CCH / 4), threads>>>(sp, out);
}